// round 1
// baseline (speedup 1.0000x reference)
#include <cuda_runtime.h>
#include <cstdint>
#include <cstddef>

typedef unsigned long long ull;

#define B_DIM 4096
#define L_DIM 64
#define D_EMB 256
#define H_DIM 20
#define R_TOT (B_DIM * L_DIM)  // 262144 rows

// ---------------- persistent device scratch (no runtime allocation) ----------
__device__ float g_qs[R_TOT * H_DIM];          // 21 MB
__device__ float g_ks[R_TOT * H_DIM];          // 21 MB
__device__ float g_vs[R_TOT * H_DIM];          // 21 MB
__device__ float g_kvs[L_DIM * H_DIM * H_DIM]; // 25600
__device__ float g_ks_sum[L_DIM * H_DIM];      // 1280
__device__ float g_vs_sum[L_DIM * H_DIM];      // 1280
__device__ float g_sums[4];                    // sum_q, ssq_q, sum_k, ssq_k

// ---------------- packed fp32x2 helpers (Blackwell FFMA2) --------------------
__device__ __forceinline__ ull pack2(float lo, float hi) {
    ull r;
    asm("mov.b64 %0, {%1,%2};" : "=l"(r) : "f"(lo), "f"(hi));
    return r;
}
__device__ __forceinline__ float2 unpack2(ull v) {
    float2 f;
    asm("mov.b64 {%0,%1}, %2;" : "=f"(f.x), "=f"(f.y) : "l"(v));
    return f;
}
__device__ __forceinline__ void fma2(ull& d, ull a, ull b) {
    asm("fma.rn.f32x2 %0, %1, %2, %3;" : "=l"(d) : "l"(a), "l"(b), "l"(d));
}

// ---------------- kernel 0: clear reduction accumulators ---------------------
__global__ void zero_kernel() {
    int i = blockIdx.x * blockDim.x + threadIdx.x;
    if (i < L_DIM * H_DIM * H_DIM) g_kvs[i] = 0.0f;
    if (i < L_DIM * H_DIM) { g_ks_sum[i] = 0.0f; g_vs_sum[i] = 0.0f; }
    if (i < 4) g_sums[i] = 0.0f;
}

// ---------------- kernel 1: projection [R,256] x [256,20] + b ----------------
// One thread per row. W in SMEM as fp32-pairs, warp-uniform LDS (broadcast).
// Optionally accumulates global sum / sum-of-squares (for norm + cond).
__device__ __forceinline__ void step10(ull* acc, float x, const ull* w) {
    ull xx = pack2(x, x);
#pragma unroll
    for (int j = 0; j < 10; j++) fma2(acc[j], xx, w[j]);
}

__global__ __launch_bounds__(256) void proj_kernel(
    const float* __restrict__ in, const float* __restrict__ W,
    const float* __restrict__ bias, int sel, int sumsBase) {
    __shared__ ull Ws2[D_EMB * H_DIM / 2];  // 2560 pairs = 20 KB
    __shared__ float bs[H_DIM];

    int tid = threadIdx.x;
    const ull* W64 = (const ull*)W;
    for (int i = tid; i < D_EMB * H_DIM / 2; i += 256) Ws2[i] = W64[i];
    if (tid < H_DIM) bs[tid] = bias[tid];
    __syncthreads();

    float* outp = (sel == 0) ? g_qs : (sel == 1) ? g_ks : g_vs;

    size_t r = (size_t)blockIdx.x * 256 + tid;
    const float4* row = (const float4*)(in + r * (size_t)D_EMB);

    ull acc[10];
#pragma unroll
    for (int j = 0; j < 10; j++) acc[j] = pack2(bs[2 * j], bs[2 * j + 1]);

#pragma unroll 2
    for (int d4 = 0; d4 < D_EMB / 4; d4++) {
        float4 x = row[d4];
        step10(acc, x.x, &Ws2[(d4 * 4 + 0) * 10]);
        step10(acc, x.y, &Ws2[(d4 * 4 + 1) * 10]);
        step10(acc, x.z, &Ws2[(d4 * 4 + 2) * 10]);
        step10(acc, x.w, &Ws2[(d4 * 4 + 3) * 10]);
    }

    float o[H_DIM];
#pragma unroll
    for (int j = 0; j < 10; j++) {
        float2 f = unpack2(acc[j]);
        o[2 * j] = f.x;
        o[2 * j + 1] = f.y;
    }

    float4* orow = (float4*)(outp + r * H_DIM);  // r*80 bytes, 16B-aligned
    orow[0] = make_float4(o[0], o[1], o[2], o[3]);
    orow[1] = make_float4(o[4], o[5], o[6], o[7]);
    orow[2] = make_float4(o[8], o[9], o[10], o[11]);
    orow[3] = make_float4(o[12], o[13], o[14], o[15]);
    orow[4] = make_float4(o[16], o[17], o[18], o[19]);

    if (sumsBase >= 0) {
        float s1 = 0.0f, s2 = 0.0f;
#pragma unroll
        for (int h = 0; h < H_DIM; h++) {
            s1 += o[h];
            s2 = fmaf(o[h], o[h], s2);
        }
#pragma unroll
        for (int off = 16; off >= 1; off >>= 1) {
            s1 += __shfl_xor_sync(0xffffffffu, s1, off);
            s2 += __shfl_xor_sync(0xffffffffu, s2, off);
        }
        if ((tid & 31) == 0) {
            atomicAdd(&g_sums[sumsBase], s1);
            atomicAdd(&g_sums[sumsBase + 1], s2);
        }
    }
}

// ---------------- kernel 2: kvs[l] = ks[:,l,:]^T @ vs[:,l,:]  (+ ks/vs sums) -
// grid (16 n-chunks, 64 l). Block 512: stages 32 rows of ks/vs in SMEM,
// 400 threads each own one (m,d) cell of the 20x20 accumulator.
__global__ __launch_bounds__(512) void kvs_kernel() {
    __shared__ float ks_s[32 * H_DIM];
    __shared__ float vs_s[32 * H_DIM];

    int tid = threadIdx.x;
    int l = blockIdx.y;
    int n0 = blockIdx.x * 256;
    int m = tid / H_DIM, d = tid % H_DIM;
    bool active = tid < H_DIM * H_DIM;

    float acc = 0.0f, sk = 0.0f, sv = 0.0f;

    for (int nb = 0; nb < 256; nb += 32) {
        __syncthreads();
        for (int i = tid; i < 32 * H_DIM; i += 512) {
            int rr = i / H_DIM, mm = i % H_DIM;
            size_t base = ((size_t)(n0 + nb + rr) * L_DIM + l) * H_DIM + mm;
            ks_s[i] = g_ks[base];
            vs_s[i] = g_vs[base];
        }
        __syncthreads();
        if (active) {
#pragma unroll
            for (int i = 0; i < 32; i++) {
                float kv = ks_s[i * H_DIM + m];
                float vv = vs_s[i * H_DIM + d];
                acc = fmaf(kv, vv, acc);
                if (d == 0) sk += kv;
                if (m == 0) sv += vv;
            }
        }
    }

    if (active) {
        atomicAdd(&g_kvs[(l * H_DIM + m) * H_DIM + d], acc);
        if (d == 0) atomicAdd(&g_ks_sum[l * H_DIM + m], sk);
        if (m == 0) atomicAdd(&g_vs_sum[l * H_DIM + d], sv);
    }
}

// ---------------- kernel 4: per-row epilogue + final [20]x[20,256] GEMM ------
// grid (16 n-chunks, 64 l). One thread per row. Normalization folded into one
// late scalar `scale` (exactly equivalent since everything is linear in raw
// qs/ks). Wp, bp, kvs[l], sums all in SMEM; all LDS are warp-uniform.
__global__ __launch_bounds__(256) void final_kernel(
    const float* __restrict__ Wp, const float* __restrict__ bp,
    float* __restrict__ out) {
    __shared__ ull Wp2[H_DIM * D_EMB / 2];  // 2560 pairs = 20 KB
    __shared__ ull bp2[D_EMB / 2];          // 128
    __shared__ ull kvs2[H_DIM * H_DIM / 2]; // 200
    __shared__ float kss[H_DIM], vss[H_DIM];
    __shared__ float sc_scale;

    int tid = threadIdx.x;
    int l = blockIdx.y;

    const ull* Wp64 = (const ull*)Wp;
    for (int i = tid; i < H_DIM * D_EMB / 2; i += 256) Wp2[i] = Wp64[i];
    if (tid < D_EMB / 2) bp2[tid] = ((const ull*)bp)[tid];
    if (tid < H_DIM * H_DIM / 2) kvs2[tid] = ((const ull*)g_kvs)[l * (H_DIM * H_DIM / 2) + tid];
    if (tid < H_DIM) {
        kss[tid] = g_ks_sum[l * H_DIM + tid];
        vss[tid] = g_vs_sum[l * H_DIM + tid];
    }
    if (tid == 0) {
        bool cond = (g_sums[0] != 0.0f) && (g_sums[2] != 0.0f);
        sc_scale = cond ? 1.0f / (sqrtf(g_sums[1]) * sqrtf(g_sums[3])) : 1.0f;
    }
    __syncthreads();

    float scale = sc_scale;
    size_t n = (size_t)blockIdx.x * 256 + tid;
    size_t r = n * L_DIM + l;

    // load q row (raw qs; scale applied after the small matvec)
    const float4* qrow = (const float4*)(g_qs + r * H_DIM);
    float q[H_DIM];
#pragma unroll
    for (int i = 0; i < 5; i++) {
        float4 t = qrow[i];
        q[4 * i + 0] = t.x; q[4 * i + 1] = t.y;
        q[4 * i + 2] = t.z; q[4 * i + 3] = t.w;
    }

    // y = q @ kvs[l]  (20x20), nrm = q . ks_sum[l]
    ull y2[10];
#pragma unroll
    for (int j = 0; j < 10; j++) y2[j] = pack2(0.0f, 0.0f);
    float nrm = 0.0f;
#pragma unroll
    for (int m = 0; m < H_DIM; m++) {
        ull qq = pack2(q[m], q[m]);
#pragma unroll
        for (int j = 0; j < 10; j++) fma2(y2[j], qq, kvs2[m * 10 + j]);
        nrm = fmaf(q[m], kss[m], nrm);
    }

    float inv = 1.0f / fmaf(scale, nrm, (float)B_DIM);
    ull axx[H_DIM];
#pragma unroll
    for (int j = 0; j < 10; j++) {
        float2 f = unpack2(y2[j]);
        float a0 = fmaf(scale, f.x, vss[2 * j]) * inv;
        float a1 = fmaf(scale, f.y, vss[2 * j + 1]) * inv;
        axx[2 * j] = pack2(a0, a0);
        axx[2 * j + 1] = pack2(a1, a1);
    }

    // out[r, :] = attn @ Wp + bp   (Wp rows broadcast from SMEM)
    ull* orow = (ull*)(out + r * (size_t)D_EMB);
#pragma unroll 1
    for (int c = 0; c < 32; c++) {  // 8 output floats per chunk
        ull a0 = bp2[c * 4 + 0], a1 = bp2[c * 4 + 1];
        ull a2 = bp2[c * 4 + 2], a3 = bp2[c * 4 + 3];
#pragma unroll
        for (int h = 0; h < H_DIM; h++) {
            const ull* wrow = &Wp2[h * (D_EMB / 2) + c * 4];
            fma2(a0, axx[h], wrow[0]);
            fma2(a1, axx[h], wrow[1]);
            fma2(a2, axx[h], wrow[2]);
            fma2(a3, axx[h], wrow[3]);
        }
        ulonglong2* st = (ulonglong2*)(orow + c * 4);  // 16B aligned
        st[0] = make_ulonglong2(a0, a1);
        st[1] = make_ulonglong2(a2, a3);
    }
}

// ---------------- launch ------------------------------------------------------
extern "C" void kernel_launch(void* const* d_in, const int* in_sizes, int n_in,
                              void* d_out, int out_size) {
    const float* key   = (const float*)d_in[0];
    const float* value = (const float*)d_in[1];
    const float* query = (const float*)d_in[2];
    const float* Wk    = (const float*)d_in[3];
    const float* bk    = (const float*)d_in[4];
    const float* Wq    = (const float*)d_in[5];
    const float* bq    = (const float*)d_in[6];
    const float* Wv    = (const float*)d_in[7];
    const float* bv    = (const float*)d_in[8];
    const float* Wp    = (const float*)d_in[9];
    const float* bp    = (const float*)d_in[10];
    float* out = (float*)d_out;

    zero_kernel<<<100, 256>>>();

    const int PROJ_BLOCKS = R_TOT / 256;  // 1024
    proj_kernel<<<PROJ_BLOCKS, 256>>>(query, Wq, bq, /*sel=*/0, /*sums=*/0);
    proj_kernel<<<PROJ_BLOCKS, 256>>>(key,   Wk, bk, /*sel=*/1, /*sums=*/2);
    proj_kernel<<<PROJ_BLOCKS, 256>>>(value, Wv, bv, /*sel=*/2, /*sums=*/-1);

    kvs_kernel<<<dim3(16, 64), 512>>>();

    final_kernel<<<dim3(16, 64), 256>>>(Wp, bp, out);
}

// round 2
// speedup vs baseline: 1.1630x; 1.1630x over previous
#include <cuda_runtime.h>
#include <cstdint>
#include <cstddef>

typedef unsigned long long ull;

#define B_DIM 4096
#define L_DIM 64
#define D_EMB 256
#define H_DIM 20
#define R_TOT (B_DIM * L_DIM)  // 262144 rows

// proj tiling
#define P_THREADS 256
#define P_WARPS 8
#define P_RPW 128          // rows per warp
#define P_RPB 1024         // rows per block
#define P_KC 16            // k-chunk (floats)
#define P_XPAD 20          // floats per staged row (16 + 4 pad) -> conflict-free LDS.128

// ---------------- persistent device scratch (no runtime allocation) ----------
__device__ float g_qs[R_TOT * H_DIM];          // 21 MB
__device__ float g_ks[R_TOT * H_DIM];          // 21 MB
__device__ float g_vs[R_TOT * H_DIM];          // 21 MB
__device__ float g_kvs[L_DIM * H_DIM * H_DIM]; // 25600
__device__ float g_ks_sum[L_DIM * H_DIM];      // 1280
__device__ float g_vs_sum[L_DIM * H_DIM];      // 1280
__device__ float g_sums[4];                    // sum_q, ssq_q, sum_k, ssq_k

// ---------------- packed fp32x2 helpers (Blackwell FFMA2) --------------------
__device__ __forceinline__ ull pack2(float lo, float hi) {
    ull r;
    asm("mov.b64 %0, {%1,%2};" : "=l"(r) : "f"(lo), "f"(hi));
    return r;
}
__device__ __forceinline__ float2 unpack2(ull v) {
    float2 f;
    asm("mov.b64 {%0,%1}, %2;" : "=f"(f.x), "=f"(f.y) : "l"(v));
    return f;
}
__device__ __forceinline__ void fma2(ull& d, ull a, ull b) {
    asm("fma.rn.f32x2 %0, %1, %2, %0;" : "+l"(d) : "l"(a), "l"(b));
}

// ---------------- kernel 0: clear reduction accumulators ---------------------
__global__ void zero_kernel() {
    int i = blockIdx.x * blockDim.x + threadIdx.x;
    if (i < L_DIM * H_DIM * H_DIM) g_kvs[i] = 0.0f;
    if (i < L_DIM * H_DIM) { g_ks_sum[i] = 0.0f; g_vs_sum[i] = 0.0f; }
    if (i < 4) g_sums[i] = 0.0f;
}

// ---------------- kernel 1: projection [R,256] x [256,20] + b ----------------
// 4 rows/thread (weight LDS amortized 4x), inputs staged through SMEM with
// coalesced LDG and conflict-free padded LDS.128 readback. Weights broadcast
// from SMEM as fp32 pairs.
__global__ void __launch_bounds__(P_THREADS, 2) proj_kernel(
    const float* __restrict__ in, const float* __restrict__ W,
    const float* __restrict__ bias, float* __restrict__ outp, int sumsBase) {
    extern __shared__ char smraw[];
    ull* Ws2 = (ull*)smraw;                              // 2560 ull = 20480 B
    float* bs = (float*)(smraw + 20480);                 // 20 floats (pad to 128)
    float* xbuf = (float*)(smraw + 20608);               // 8 * 128 * 20 floats = 81920 B

    int tid = threadIdx.x;
    int w = tid >> 5, lane = tid & 31;

    const ull* W64 = (const ull*)W;
    for (int i = tid; i < D_EMB * H_DIM / 2; i += P_THREADS) Ws2[i] = W64[i];
    if (tid < H_DIM) bs[tid] = bias[tid];
    __syncthreads();

    float* xw = xbuf + w * (P_RPW * P_XPAD);
    size_t rowBase = (size_t)blockIdx.x * P_RPB + (size_t)w * P_RPW;
    const float4* src = (const float4*)(in + rowBase * D_EMB);  // 64 float4 per row

    ull acc[4][10];
#pragma unroll
    for (int r = 0; r < 4; r++)
#pragma unroll
        for (int j = 0; j < 10; j++) acc[r][j] = pack2(bs[2 * j], bs[2 * j + 1]);

#pragma unroll 1
    for (int kc = 0; kc < D_EMB / P_KC; kc++) {
        __syncwarp();
        // stage 128 rows x 16 floats, coalesced (128B-contiguous per 4 lanes)
#pragma unroll
        for (int i = 0; i < 16; i++) {
            int id = i * 32 + lane;
            int rr = id >> 2, c4 = id & 3;
            float4 v = src[rr * 64 + kc * 4 + c4];
            *(float4*)&xw[rr * P_XPAD + c4 * 4] = v;
        }
        __syncwarp();
        // compute: rows lane, lane+32, lane+64, lane+96
#pragma unroll
        for (int kk4 = 0; kk4 < 4; kk4++) {
            float4 x0 = *(const float4*)&xw[(lane)*P_XPAD + kk4 * 4];
            float4 x1 = *(const float4*)&xw[(lane + 32) * P_XPAD + kk4 * 4];
            float4 x2 = *(const float4*)&xw[(lane + 64) * P_XPAD + kk4 * 4];
            float4 x3 = *(const float4*)&xw[(lane + 96) * P_XPAD + kk4 * 4];
            const float* f0 = (const float*)&x0;
            const float* f1 = (const float*)&x1;
            const float* f2 = (const float*)&x2;
            const float* f3 = (const float*)&x3;
#pragma unroll
            for (int q = 0; q < 4; q++) {
                int k = kc * P_KC + kk4 * 4 + q;
                const ull* wrow = &Ws2[k * 10];
                ull xx0 = pack2(f0[q], f0[q]);
                ull xx1 = pack2(f1[q], f1[q]);
                ull xx2 = pack2(f2[q], f2[q]);
                ull xx3 = pack2(f3[q], f3[q]);
#pragma unroll
                for (int j = 0; j < 10; j++) {
                    ull wv = wrow[j];
                    fma2(acc[0][j], xx0, wv);
                    fma2(acc[1][j], xx1, wv);
                    fma2(acc[2][j], xx2, wv);
                    fma2(acc[3][j], xx3, wv);
                }
            }
        }
    }

    float s1 = 0.0f, s2 = 0.0f;
#pragma unroll
    for (int r = 0; r < 4; r++) {
        float o[H_DIM];
#pragma unroll
        for (int j = 0; j < 10; j++) {
            float2 f = unpack2(acc[r][j]);
            o[2 * j] = f.x;
            o[2 * j + 1] = f.y;
        }
        size_t row = rowBase + lane + 32 * r;
        float4* orow = (float4*)(outp + row * H_DIM);  // 80B rows, 16B aligned
        orow[0] = make_float4(o[0], o[1], o[2], o[3]);
        orow[1] = make_float4(o[4], o[5], o[6], o[7]);
        orow[2] = make_float4(o[8], o[9], o[10], o[11]);
        orow[3] = make_float4(o[12], o[13], o[14], o[15]);
        orow[4] = make_float4(o[16], o[17], o[18], o[19]);
        if (sumsBase >= 0) {
#pragma unroll
            for (int h = 0; h < H_DIM; h++) {
                s1 += o[h];
                s2 = fmaf(o[h], o[h], s2);
            }
        }
    }

    if (sumsBase >= 0) {
#pragma unroll
        for (int off = 16; off >= 1; off >>= 1) {
            s1 += __shfl_xor_sync(0xffffffffu, s1, off);
            s2 += __shfl_xor_sync(0xffffffffu, s2, off);
        }
        if (lane == 0) {
            atomicAdd(&g_sums[sumsBase], s1);
            atomicAdd(&g_sums[sumsBase + 1], s2);
        }
    }
}

// ---------------- kernel 2: kvs[l] = ks[:,l,:]^T @ vs[:,l,:]  (+ ks/vs sums) -
__global__ __launch_bounds__(512) void kvs_kernel() {
    __shared__ float ks_s[32 * H_DIM];
    __shared__ float vs_s[32 * H_DIM];

    int tid = threadIdx.x;
    int l = blockIdx.y;
    int n0 = blockIdx.x * 256;
    int m = tid / H_DIM, d = tid % H_DIM;
    bool active = tid < H_DIM * H_DIM;

    float acc = 0.0f, sk = 0.0f, sv = 0.0f;

    for (int nb = 0; nb < 256; nb += 32) {
        __syncthreads();
        for (int i = tid; i < 32 * H_DIM; i += 512) {
            int rr = i / H_DIM, mm = i % H_DIM;
            size_t base = ((size_t)(n0 + nb + rr) * L_DIM + l) * H_DIM + mm;
            ks_s[i] = g_ks[base];
            vs_s[i] = g_vs[base];
        }
        __syncthreads();
        if (active) {
#pragma unroll
            for (int i = 0; i < 32; i++) {
                float kv = ks_s[i * H_DIM + m];
                float vv = vs_s[i * H_DIM + d];
                acc = fmaf(kv, vv, acc);
                if (d == 0) sk += kv;
                if (m == 0) sv += vv;
            }
        }
    }

    if (active) {
        atomicAdd(&g_kvs[(l * H_DIM + m) * H_DIM + d], acc);
        if (d == 0) atomicAdd(&g_ks_sum[l * H_DIM + m], sk);
        if (m == 0) atomicAdd(&g_vs_sum[l * H_DIM + d], sv);
    }
}

// ---------------- kernel 4: per-row epilogue + final [20]x[20,256] GEMM ------
// Phase A: thread-per-row small matvec (q@kvs + normalizer) -> attn row in SMEM.
// Phase B: warp-cooperative 20x256 output GEMM with Wp slice in REGISTERS and
// fully coalesced 16B/lane stores.
__global__ __launch_bounds__(256, 2) void final_kernel(
    const float* __restrict__ Wp, const float* __restrict__ bp,
    float* __restrict__ out) {
    __shared__ float attn_s[256 * H_DIM];   // 20 KB, stride-20 conflict-free
    __shared__ ull kvs2[H_DIM * H_DIM / 2]; // 200
    __shared__ float kss[H_DIM], vss[H_DIM];
    __shared__ float sc_scale;

    int tid = threadIdx.x;
    int w = tid >> 5, lane = tid & 31;
    int l = blockIdx.y;
    int n0 = blockIdx.x * 256;

    // ---- load per-warp Wp slice into registers (coalesced 16B/lane) ----
    int half = w & 1;                 // which 128-col half this warp owns
    const ulonglong2* Wp128 = (const ulonglong2*)Wp;  // 64 x ulonglong2 per h-row
    ull wx[H_DIM], wy[H_DIM];
#pragma unroll
    for (int h = 0; h < H_DIM; h++) {
        ulonglong2 t = Wp128[h * 64 + half * 32 + lane];
        wx[h] = t.x;
        wy[h] = t.y;
    }
    ulonglong2 bpr = ((const ulonglong2*)bp)[half * 32 + lane];

    if (tid < H_DIM * H_DIM / 2)
        kvs2[tid] = ((const ull*)g_kvs)[l * (H_DIM * H_DIM / 2) + tid];
    if (tid < H_DIM) {
        kss[tid] = g_ks_sum[l * H_DIM + tid];
        vss[tid] = g_vs_sum[l * H_DIM + tid];
    }
    if (tid == 0) {
        bool cond = (g_sums[0] != 0.0f) && (g_sums[2] != 0.0f);
        sc_scale = cond ? 1.0f / (sqrtf(g_sums[1]) * sqrtf(g_sums[3])) : 1.0f;
    }
    __syncthreads();

    // ---- phase A: attn row for this thread's row ----
    {
        float scale = sc_scale;
        size_t n = (size_t)(n0 + tid);
        size_t r = n * L_DIM + l;
        const float4* qrow = (const float4*)(g_qs + r * H_DIM);
        float q[H_DIM];
#pragma unroll
        for (int i = 0; i < 5; i++) {
            float4 t = qrow[i];
            q[4 * i + 0] = t.x; q[4 * i + 1] = t.y;
            q[4 * i + 2] = t.z; q[4 * i + 3] = t.w;
        }
        ull y2[10];
#pragma unroll
        for (int j = 0; j < 10; j++) y2[j] = pack2(0.0f, 0.0f);
        float nrm = 0.0f;
#pragma unroll
        for (int m = 0; m < H_DIM; m++) {
            ull qq = pack2(q[m], q[m]);
#pragma unroll
            for (int j = 0; j < 10; j++) fma2(y2[j], qq, kvs2[m * 10 + j]);
            nrm = fmaf(q[m], kss[m], nrm);
        }
        float inv = 1.0f / fmaf(scale, nrm, (float)B_DIM);
        float* arow = attn_s + tid * H_DIM;
#pragma unroll
        for (int j = 0; j < 10; j++) {
            float2 f = unpack2(y2[j]);
            arow[2 * j] = fmaf(scale, f.x, vss[2 * j]) * inv;
            arow[2 * j + 1] = fmaf(scale, f.y, vss[2 * j + 1]) * inv;
        }
    }
    __syncthreads();

    // ---- phase B: warp-pair (w>>1) handles 64 rows; this warp does its half -
    int g = w >> 1;
#pragma unroll 1
    for (int rr = 0; rr < 64; rr++) {
        int rowInBlk = g * 64 + rr;
        const float* arow = attn_s + rowInBlk * H_DIM;
        ull a0 = bpr.x, a1 = bpr.y;
#pragma unroll
        for (int h = 0; h < H_DIM; h++) {
            float a = arow[h];              // warp-uniform broadcast LDS
            ull aa = pack2(a, a);
            fma2(a0, aa, wx[h]);
            fma2(a1, aa, wy[h]);
        }
        size_t r = (size_t)(n0 + rowInBlk) * L_DIM + l;
        ulonglong2* st = (ulonglong2*)(out + r * D_EMB + half * 128 + lane * 4);
        *st = make_ulonglong2(a0, a1);      // coalesced 512B per warp
    }
}

// ---------------- launch ------------------------------------------------------
extern "C" void kernel_launch(void* const* d_in, const int* in_sizes, int n_in,
                              void* d_out, int out_size) {
    const float* key   = (const float*)d_in[0];
    const float* value = (const float*)d_in[1];
    const float* query = (const float*)d_in[2];
    const float* Wk    = (const float*)d_in[3];
    const float* bk    = (const float*)d_in[4];
    const float* Wq    = (const float*)d_in[5];
    const float* bq    = (const float*)d_in[6];
    const float* Wv    = (const float*)d_in[7];
    const float* bv    = (const float*)d_in[8];
    const float* Wp    = (const float*)d_in[9];
    const float* bp    = (const float*)d_in[10];
    float* out = (float*)d_out;

    // qs / ks / vs scratch pointers
    float *qs_p, *ks_p, *vs_p;
    cudaGetSymbolAddress((void**)&qs_p, g_qs);
    cudaGetSymbolAddress((void**)&ks_p, g_ks);
    cudaGetSymbolAddress((void**)&vs_p, g_vs);

    const int PROJ_SMEM = 20608 + P_WARPS * P_RPW * P_XPAD * 4;  // 102528
    cudaFuncSetAttribute(proj_kernel, cudaFuncAttributeMaxDynamicSharedMemorySize,
                         PROJ_SMEM);

    zero_kernel<<<100, 256>>>();

    const int PROJ_BLOCKS = R_TOT / P_RPB;  // 256
    proj_kernel<<<PROJ_BLOCKS, P_THREADS, PROJ_SMEM>>>(query, Wq, bq, qs_p, 0);
    proj_kernel<<<PROJ_BLOCKS, P_THREADS, PROJ_SMEM>>>(key,   Wk, bk, ks_p, 2);
    proj_kernel<<<PROJ_BLOCKS, P_THREADS, PROJ_SMEM>>>(value, Wv, bv, vs_p, -1);

    kvs_kernel<<<dim3(16, 64), 512>>>();

    final_kernel<<<dim3(16, 64), 256>>>(Wp, bp, out);
}

// round 7
// speedup vs baseline: 1.2165x; 1.0460x over previous
#include <cuda_runtime.h>
#include <cstdint>
#include <cstddef>

typedef unsigned long long ull;

#define B_DIM 4096
#define L_DIM 64
#define D_EMB 256
#define H_DIM 20
#define R_TOT (B_DIM * L_DIM)  // 262144 rows

// proj tiling
#define P_THREADS 256
#define P_WARPS 8
#define P_RPW 64           // rows per warp (2 per thread)
#define P_RPB 512          // rows per block
#define P_KC 16            // k-chunk (floats)
#define P_XPAD 20          // staged row stride (16 + 4 pad) -> conflict-free LDS.128
#define XBUF_WARP (P_RPW * P_XPAD)            // 1280 floats per warp per buffer
#define XBUF_BUF (P_WARPS * XBUF_WARP)        // 10240 floats per buffer

// ---------------- persistent device scratch (no runtime allocation) ----------
__device__ float g_qs[R_TOT * H_DIM];          // 21 MB
__device__ float g_ks[R_TOT * H_DIM];          // 21 MB
__device__ float g_vs[R_TOT * H_DIM];          // 21 MB
__device__ float g_kvs[L_DIM * H_DIM * H_DIM]; // 25600
__device__ float g_ks_sum[L_DIM * H_DIM];      // 1280
__device__ float g_vs_sum[L_DIM * H_DIM];      // 1280
__device__ float g_sums[4];                    // sum_q, ssq_q, sum_k, ssq_k

// ---------------- packed fp32x2 helpers (Blackwell FFMA2) --------------------
__device__ __forceinline__ ull pack2(float lo, float hi) {
    ull r;
    asm("mov.b64 %0, {%1,%2};" : "=l"(r) : "f"(lo), "f"(hi));
    return r;
}
__device__ __forceinline__ float2 unpack2(ull v) {
    float2 f;
    asm("mov.b64 {%0,%1}, %2;" : "=f"(f.x), "=f"(f.y) : "l"(v));
    return f;
}
__device__ __forceinline__ void fma2(ull& d, ull a, ull b) {
    asm("fma.rn.f32x2 %0, %1, %2, %0;" : "+l"(d) : "l"(a), "l"(b));
}

// ---------------- kernel 0: clear reduction accumulators ---------------------
__global__ void zero_kernel() {
    int i = blockIdx.x * blockDim.x + threadIdx.x;
    if (i < L_DIM * H_DIM * H_DIM) g_kvs[i] = 0.0f;
    if (i < L_DIM * H_DIM) { g_ks_sum[i] = 0.0f; g_vs_sum[i] = 0.0f; }
    if (i < 4) g_sums[i] = 0.0f;
}

// ---------------- kernel 1: projection [R,256] x [256,20] + b ----------------
// 2 rows/thread. Register-prefetch software pipeline (LDG next chunk into regs
// while computing current chunk from SMEM), double-buffered per-warp staging,
// warp-scope sync only. Weights broadcast from SMEM via LDS.128 pairs.
__global__ void __launch_bounds__(P_THREADS, 2) proj_kernel(
    const float* __restrict__ in, const float* __restrict__ W,
    const float* __restrict__ bias, float* __restrict__ outp, int sumsBase) {
    extern __shared__ char smraw[];
    ull* Ws2 = (ull*)smraw;                      // 2560 ull = 20480 B
    float* bs = (float*)(smraw + 20480);         // 20 floats (pad to 128)
    float* xbuf = (float*)(smraw + 20608);       // 2 * 10240 floats = 81920 B

    int tid = threadIdx.x;
    int w = tid >> 5, lane = tid & 31;

    const ull* W64 = (const ull*)W;
    for (int i = tid; i < D_EMB * H_DIM / 2; i += P_THREADS) Ws2[i] = W64[i];
    if (tid < H_DIM) bs[tid] = bias[tid];
    __syncthreads();

    size_t rowBase = (size_t)blockIdx.x * P_RPB + (size_t)w * P_RPW;
    const float* src = in + rowBase * D_EMB;

    float* xw[2];
    xw[0] = xbuf + w * XBUF_WARP;
    xw[1] = xbuf + XBUF_BUF + w * XBUF_WARP;

    // lane -> 8 segments of 16B per chunk: seg s = i*32+lane, row=s>>2, c4=s&3
    int seg_row[8], seg_c4[8];
#pragma unroll
    for (int i = 0; i < 8; i++) {
        int s = i * 32 + lane;
        seg_row[i] = s >> 2;
        seg_c4[i] = s & 3;
    }

    ull acc[2][10];
#pragma unroll
    for (int r = 0; r < 2; r++)
#pragma unroll
        for (int j = 0; j < 10; j++) acc[r][j] = pack2(bs[2 * j], bs[2 * j + 1]);

    // prologue: prefetch chunk 0 into registers
    float4 pf[8];
#pragma unroll
    for (int i = 0; i < 8; i++)
        pf[i] = *(const float4*)(src + seg_row[i] * D_EMB + seg_c4[i] * 4);

#pragma unroll 1
    for (int kc = 0; kc < D_EMB / P_KC; kc++) {
        float* xc = xw[kc & 1];
        // store prefetched chunk to this buffer. Safe vs. readers of this
        // buffer (iter kc-2): the syncwarp in iter kc-1 ordered them.
#pragma unroll
        for (int i = 0; i < 8; i++)
            *(float4*)&xc[seg_row[i] * P_XPAD + seg_c4[i] * 4] = pf[i];
        __syncwarp();

        // prefetch NEXT chunk (long-latency LDGs overlap the compute below)
        if (kc < D_EMB / P_KC - 1) {
            int koff = (kc + 1) * P_KC;
#pragma unroll
            for (int i = 0; i < 8; i++)
                pf[i] = *(const float4*)(src + seg_row[i] * D_EMB + koff +
                                         seg_c4[i] * 4);
        }

        // compute current chunk
#pragma unroll
        for (int kk4 = 0; kk4 < 4; kk4++) {
            float4 xa = *(const float4*)&xc[lane * P_XPAD + kk4 * 4];
            float4 xb = *(const float4*)&xc[(lane + 32) * P_XPAD + kk4 * 4];
            const float* fa = (const float*)&xa;
            const float* fb = (const float*)&xb;
#pragma unroll
            for (int q = 0; q < 4; q++) {
                int k = kc * P_KC + kk4 * 4 + q;
                const ulonglong2* wq = (const ulonglong2*)&Ws2[k * 10];
                ull xxa = pack2(fa[q], fa[q]);
                ull xxb = pack2(fb[q], fb[q]);
#pragma unroll
                for (int j2 = 0; j2 < 5; j2++) {
                    ulonglong2 t = wq[j2];  // broadcast LDS.128
                    fma2(acc[0][2 * j2], xxa, t.x);
                    fma2(acc[0][2 * j2 + 1], xxa, t.y);
                    fma2(acc[1][2 * j2], xxb, t.x);
                    fma2(acc[1][2 * j2 + 1], xxb, t.y);
                }
            }
        }
        __syncwarp();  // all lanes done reading xc before it is overwritten
    }

    float s1 = 0.0f, s2 = 0.0f;
#pragma unroll
    for (int r = 0; r < 2; r++) {
        float o[H_DIM];
#pragma unroll
        for (int j = 0; j < 10; j++) {
            float2 f = unpack2(acc[r][j]);
            o[2 * j] = f.x;
            o[2 * j + 1] = f.y;
        }
        size_t row = rowBase + lane + 32 * r;
        float4* orow = (float4*)(outp + row * H_DIM);  // 80B rows, 16B aligned
        orow[0] = make_float4(o[0], o[1], o[2], o[3]);
        orow[1] = make_float4(o[4], o[5], o[6], o[7]);
        orow[2] = make_float4(o[8], o[9], o[10], o[11]);
        orow[3] = make_float4(o[12], o[13], o[14], o[15]);
        orow[4] = make_float4(o[16], o[17], o[18], o[19]);
        if (sumsBase >= 0) {
#pragma unroll
            for (int h = 0; h < H_DIM; h++) {
                s1 += o[h];
                s2 = fmaf(o[h], o[h], s2);
            }
        }
    }

    if (sumsBase >= 0) {
#pragma unroll
        for (int off = 16; off >= 1; off >>= 1) {
            s1 += __shfl_xor_sync(0xffffffffu, s1, off);
            s2 += __shfl_xor_sync(0xffffffffu, s2, off);
        }
        if (lane == 0) {
            atomicAdd(&g_sums[sumsBase], s1);
            atomicAdd(&g_sums[sumsBase + 1], s2);
        }
    }
}

// ---------------- kernel 2: kvs[l] = ks[:,l,:]^T @ vs[:,l,:]  (+ ks/vs sums) -
__global__ __launch_bounds__(512) void kvs_kernel() {
    __shared__ float ks_s[32 * H_DIM];
    __shared__ float vs_s[32 * H_DIM];

    int tid = threadIdx.x;
    int l = blockIdx.y;
    int n0 = blockIdx.x * 256;
    int m = tid / H_DIM, d = tid % H_DIM;
    bool active = tid < H_DIM * H_DIM;

    float acc = 0.0f, sk = 0.0f, sv = 0.0f;

    for (int nb = 0; nb < 256; nb += 32) {
        __syncthreads();
        for (int i = tid; i < 32 * H_DIM; i += 512) {
            int rr = i / H_DIM, mm = i % H_DIM;
            size_t base = ((size_t)(n0 + nb + rr) * L_DIM + l) * H_DIM + mm;
            ks_s[i] = g_ks[base];
            vs_s[i] = g_vs[base];
        }
        __syncthreads();
        if (active) {
#pragma unroll
            for (int i = 0; i < 32; i++) {
                float kv = ks_s[i * H_DIM + m];
                float vv = vs_s[i * H_DIM + d];
                acc = fmaf(kv, vv, acc);
                if (d == 0) sk += kv;
                if (m == 0) sv += vv;
            }
        }
    }

    if (active) {
        atomicAdd(&g_kvs[(l * H_DIM + m) * H_DIM + d], acc);
        if (d == 0) atomicAdd(&g_ks_sum[l * H_DIM + m], sk);
        if (m == 0) atomicAdd(&g_vs_sum[l * H_DIM + d], sv);
    }
}

// ---------------- kernel 4: per-row epilogue + final [20]x[20,256] GEMM ------
__global__ __launch_bounds__(256, 2) void final_kernel(
    const float* __restrict__ Wp, const float* __restrict__ bp,
    float* __restrict__ out) {
    __shared__ float attn_s[256 * H_DIM];   // 20 KB
    __shared__ ull kvs2[H_DIM * H_DIM / 2]; // 200
    __shared__ float kss[H_DIM], vss[H_DIM];
    __shared__ float sc_scale;

    int tid = threadIdx.x;
    int w = tid >> 5, lane = tid & 31;
    int l = blockIdx.y;
    int n0 = blockIdx.x * 256;

    int half = w & 1;
    const ulonglong2* Wp128 = (const ulonglong2*)Wp;
    ull wx[H_DIM], wy[H_DIM];
#pragma unroll
    for (int h = 0; h < H_DIM; h++) {
        ulonglong2 t = Wp128[h * 64 + half * 32 + lane];
        wx[h] = t.x;
        wy[h] = t.y;
    }
    ulonglong2 bpr = ((const ulonglong2*)bp)[half * 32 + lane];

    if (tid < H_DIM * H_DIM / 2)
        kvs2[tid] = ((const ull*)g_kvs)[l * (H_DIM * H_DIM / 2) + tid];
    if (tid < H_DIM) {
        kss[tid] = g_ks_sum[l * H_DIM + tid];
        vss[tid] = g_vs_sum[l * H_DIM + tid];
    }
    if (tid == 0) {
        bool cond = (g_sums[0] != 0.0f) && (g_sums[2] != 0.0f);
        sc_scale = cond ? 1.0f / (sqrtf(g_sums[1]) * sqrtf(g_sums[3])) : 1.0f;
    }
    __syncthreads();

    {
        float scale = sc_scale;
        size_t n = (size_t)(n0 + tid);
        size_t r = n * L_DIM + l;
        const float4* qrow = (const float4*)(g_qs + r * H_DIM);
        float q[H_DIM];
#pragma unroll
        for (int i = 0; i < 5; i++) {
            float4 t = qrow[i];
            q[4 * i + 0] = t.x; q[4 * i + 1] = t.y;
            q[4 * i + 2] = t.z; q[4 * i + 3] = t.w;
        }
        ull y2[10];
#pragma unroll
        for (int j = 0; j < 10; j++) y2[j] = pack2(0.0f, 0.0f);
        float nrm = 0.0f;
#pragma unroll
        for (int m = 0; m < H_DIM; m++) {
            ull qq = pack2(q[m], q[m]);
#pragma unroll
            for (int j = 0; j < 10; j++) fma2(y2[j], qq, kvs2[m * 10 + j]);
            nrm = fmaf(q[m], kss[m], nrm);
        }
        float inv = 1.0f / fmaf(scale, nrm, (float)B_DIM);
        float* arow = attn_s + tid * H_DIM;
#pragma unroll
        for (int j = 0; j < 10; j++) {
            float2 f = unpack2(y2[j]);
            arow[2 * j] = fmaf(scale, f.x, vss[2 * j]) * inv;
            arow[2 * j + 1] = fmaf(scale, f.y, vss[2 * j + 1]) * inv;
        }
    }
    __syncthreads();

    int g = w >> 1;
#pragma unroll 1
    for (int rr = 0; rr < 64; rr++) {
        int rowInBlk = g * 64 + rr;
        const float* arow = attn_s + rowInBlk * H_DIM;
        ull a0 = bpr.x, a1 = bpr.y;
#pragma unroll
        for (int h = 0; h < H_DIM; h++) {
            float a = arow[h];
            ull aa = pack2(a, a);
            fma2(a0, aa, wx[h]);
            fma2(a1, aa, wy[h]);
        }
        size_t r = (size_t)(n0 + rowInBlk) * L_DIM + l;
        ulonglong2* st = (ulonglong2*)(out + r * D_EMB + half * 128 + lane * 4);
        *st = make_ulonglong2(a0, a1);
    }
}

// ---------------- launch ------------------------------------------------------
extern "C" void kernel_launch(void* const* d_in, const int* in_sizes, int n_in,
                              void* d_out, int out_size) {
    const float* key   = (const float*)d_in[0];
    const float* value = (const float*)d_in[1];
    const float* query = (const float*)d_in[2];
    const float* Wk    = (const float*)d_in[3];
    const float* bk    = (const float*)d_in[4];
    const float* Wq    = (const float*)d_in[5];
    const float* bq    = (const float*)d_in[6];
    const float* Wv    = (const float*)d_in[7];
    const float* bv    = (const float*)d_in[8];
    const float* Wp    = (const float*)d_in[9];
    const float* bp    = (const float*)d_in[10];
    float* out = (float*)d_out;

    float *qs_p, *ks_p, *vs_p;
    cudaGetSymbolAddress((void**)&qs_p, g_qs);
    cudaGetSymbolAddress((void**)&ks_p, g_ks);
    cudaGetSymbolAddress((void**)&vs_p, g_vs);

    const int PROJ_SMEM = 20608 + 2 * XBUF_BUF * 4;  // 20608 + 81920 = 102528
    cudaFuncSetAttribute(proj_kernel, cudaFuncAttributeMaxDynamicSharedMemorySize,
                         PROJ_SMEM);

    zero_kernel<<<100, 256>>>();

    const int PROJ_BLOCKS = R_TOT / P_RPB;  // 512
    proj_kernel<<<PROJ_BLOCKS, P_THREADS, PROJ_SMEM>>>(query, Wq, bq, qs_p, 0);
    proj_kernel<<<PROJ_BLOCKS, P_THREADS, PROJ_SMEM>>>(key,   Wk, bk, ks_p, 2);
    proj_kernel<<<PROJ_BLOCKS, P_THREADS, PROJ_SMEM>>>(value, Wv, bv, vs_p, -1);

    kvs_kernel<<<dim3(16, 64), 512>>>();

    final_kernel<<<dim3(16, 64), 256>>>(Wp, bp, out);
}